// round 13
// baseline (speedup 1.0000x reference)
#include <cuda_runtime.h>
#include <math.h>

// Problem constants
#define NB   512
#define NA   4
#define NE   10
#define NH   256
#define NOBS 2
#define NPHY 3
#define NG   3
#define NMV  2
#define NT   10
#define MP   (NB*NA*NE)   // 20480 rows for physical module
#define MA_  (NB*NA)      // 2048 rows for action module
#define KA   528          // padded action inner dim (256 ma + 256 feat + 3 goals + 13 pad)

// ---------------- scratch (device globals; no runtime allocation) ----------------
__device__ float g_giP  [MP*768];       // precomputed x-side GRU terms (+biases folded)
__device__ float g_WhhT [256*768];      // W_hh_p^T  : [k][n]
__device__ float g_WcatT[KA*1024];      // fused action weights: strips r,z,in,hn
__device__ float g_WfcPT[256*256];
__device__ float g_WfcAT[256*256];
__device__ float g_Wm1T [256*256];
__device__ float g_mp   [2*MP*NH];      // physical memory ping-pong
__device__ float g_ma   [2*MA_*NH];     // action memory ping-pong
__device__ float g_proc [MP*NH];
__device__ float g_feat [MA_*NH];
__device__ float g_cat  [MA_*KA];
__device__ float g_proca[MA_*NH];
__device__ float g_m1   [MA_*NH];

__device__ __forceinline__ float sigf(float x){ return 1.f/(1.f+expf(-x)); }
__device__ __forceinline__ float eluf(float x){ return x>0.f ? x : expm1f(x); }

// ---------------- precompute kernels ----------------
// W [R][C] row-major -> WT [C][R]  (so WT[k*R + n] = W[n][k])
__global__ void k_transpose(const float* __restrict__ W, float* __restrict__ WT, int R, int C){
  int idx = blockIdx.x*blockDim.x + threadIdx.x;
  if (idx >= R*C) return;
  int r = idx / C, c = idx % C;
  WT[c*R + r] = W[idx];
}

// Fused action weight matrix: rows k in [0,528), cols c in [0,1024)
// strip = c>>8, j = c&255
//  strip 0 (r): k<256 -> W_hh_a[j][k];      256<=k<515 -> W_ih_a[j][k-256]
//  strip 1 (z): same with output row 256+j
//  strip 2 (in): only x part  -> W_ih_a[512+j][k-256]
//  strip 3 (hn): only ma part -> W_hh_a[512+j][k]
__global__ void k_wcat(const float* __restrict__ Wih, const float* __restrict__ Whh,
                       float* __restrict__ WT){
  int idx = blockIdx.x*blockDim.x + threadIdx.x;
  if (idx >= KA*1024) return;
  int k = idx >> 10, c = idx & 1023;
  int strip = c >> 8, j = c & 255;
  float v = 0.f;
  if (strip < 2){
    int orow = strip*256 + j;
    if (k < 256)      v = Whh[orow*256 + k];
    else if (k < 515) v = Wih[orow*259 + (k-256)];
  } else if (strip == 2){
    if (k >= 256 && k < 515) v = Wih[(512+j)*259 + (k-256)];
  } else {
    if (k < 256) v = Whh[(512+j)*256 + k];
  }
  WT[idx] = v;
}

// g_giP[m*768 + g*256 + j] = x_p[m] . W_ih_p[g*256+j] + b_ih (+ b_hh for r,z)
__global__ void k_giP(const float* __restrict__ obs, const float* __restrict__ phys,
                      const float* __restrict__ Wih, const float* __restrict__ bih,
                      const float* __restrict__ bhh){
  int m = blockIdx.x, j = threadIdx.x;
  int b = m / (NA*NE);
  int e = m % NE;
  float x0 = obs[m*NOBS+0], x1 = obs[m*NOBS+1];
  const float* p = phys + (b*NE + e)*NPHY;
  float x2 = p[0], x3 = p[1], x4 = p[2];
  #pragma unroll
  for (int g=0; g<3; g++){
    int o = g*256 + j;
    const float* w = Wih + o*5;
    float v = x0*w[0] + x1*w[1] + x2*w[2] + x3*w[3] + x4*w[4] + bih[o];
    if (g < 2) v += bhh[o];
    g_giP[m*768 + o] = v;
  }
}

// ---------------- tiled fp32 GEMM core ----------------
// C tile [BM x BN] = A[M x K] (lda) * B_strips, with smem staging.
// B columns come from NSTRIP strips: global col = n0 + strip*SSTRIDE + jj.
// 256 threads; thread grid (BM/TM) rows x (BN/TN) cols, BN/TN must be 16.
template<int BM,int BN,int BK,int TM,int TN,int NSTRIP,int SSTRIDE>
__device__ __forceinline__ void gemm_core(
    const float* __restrict__ A, int lda,
    const float* __restrict__ B, int ldb,
    int K, int m0, int n0,
    float* acc, float* sA, float* sB)
{
  static_assert((BM/TM)*(BN/TN) == 256, "thread grid must be 256");
  constexpr int BNS = BN / NSTRIP;
  constexpr int TNh = TN / NSTRIP;
  const int tid  = threadIdx.x;
  const int tcol = tid % (BN/TN);
  const int trow = tid / (BN/TN);
  #pragma unroll
  for (int i=0;i<TM*TN;i++) acc[i] = 0.f;

  for (int k0=0; k0<K; k0+=BK){
    // A tile: BM x BK, stored transposed sA[k][row]
    for (int idx4 = tid; idx4 < (BM*BK)/4; idx4 += 256){
      int row = idx4 / (BK/4);
      int c4  = (idx4 % (BK/4)) * 4;
      float4 v = *(const float4*)(A + (m0+row)*lda + k0 + c4);
      sA[(c4+0)*BM+row]=v.x; sA[(c4+1)*BM+row]=v.y;
      sA[(c4+2)*BM+row]=v.z; sA[(c4+3)*BM+row]=v.w;
    }
    // B tile: BK x BN, row-major in smem
    for (int idx4 = tid; idx4 < (BK*BN)/4; idx4 += 256){
      int lin = idx4*4;
      int k = lin / BN, c = lin % BN;
      int strip = c / BNS, jj = c - strip*BNS;
      float4 v = *(const float4*)(B + (k0+k)*ldb + n0 + strip*SSTRIDE + jj);
      *(float4*)(sB + k*BN + c) = v;
    }
    __syncthreads();
    #pragma unroll
    for (int kk=0; kk<BK; kk++){
      float a[TM], b[TN];
      #pragma unroll
      for (int i=0;i<TM;i++) a[i] = sA[kk*BM + trow*TM + i];
      #pragma unroll
      for (int s=0;s<NSTRIP;s++)
        #pragma unroll
        for (int t=0;t<TNh;t++) b[s*TNh+t] = sB[kk*BN + s*BNS + tcol*TNh + t];
      #pragma unroll
      for (int i=0;i<TM;i++)
        #pragma unroll
        for (int j=0;j<TN;j++)
          acc[i*TN+j] = fmaf(a[i], b[j], acc[i*TN+j]);
    }
    __syncthreads();
  }
}

// ---------------- per-step kernels ----------------
// Physical GRU: acc strips = mp @ W_hh^T (no bias). Fused gate epilogue.
// grid (160, 8), BNh=32 h-cols per block.
__global__ void __launch_bounds__(256) k_step_phys(
    const float* __restrict__ mp, float* __restrict__ hout,
    const float* __restrict__ bhh)
{
  constexpr int BM=128, BN=96, BK=16, TM=8, TN=6;
  __shared__ __align__(16) float sA[BM*BK];
  __shared__ __align__(16) float sB[BK*BN];
  float acc[TM*TN];
  int m0 = blockIdx.x*BM;
  int n0 = blockIdx.y*32;
  gemm_core<BM,BN,BK,TM,TN,3,256>(mp, 256, g_WhhT, 768, 256, m0, n0, acc, sA, sB);
  const int tcol = threadIdx.x % 16, trow = threadIdx.x / 16;
  #pragma unroll
  for (int i=0;i<TM;i++){
    int m = m0 + trow*TM + i;
    const float* gi = g_giP + m*768;
    #pragma unroll
    for (int t=0;t<2;t++){
      int j = n0 + tcol*2 + t;
      float r = sigf(acc[i*6 + 0*2 + t] + gi[j]);
      float z = sigf(acc[i*6 + 1*2 + t] + gi[256+j]);
      float n = tanhf(gi[512+j] + r*(acc[i*6 + 2*2 + t] + bhh[512+j]));
      hout[m*256+j] = (1.f - z)*n + z*mp[m*256+j];
    }
  }
}

// Generic X @ WT + bias, ELU epilogue
template<int BM,int BN,int TM,int TN>
__global__ void __launch_bounds__(256) k_fc_elu(
    const float* __restrict__ X, const float* __restrict__ WT,
    const float* __restrict__ bias, float* __restrict__ Y)
{
  constexpr int BK=16;
  __shared__ __align__(16) float sA[BM*BK];
  __shared__ __align__(16) float sB[BK*BN];
  float acc[TM*TN];
  int m0 = blockIdx.x*BM, n0 = blockIdx.y*BN;
  gemm_core<BM,BN,BK,TM,TN,1,0>(X, 256, WT, 256, 256, m0, n0, acc, sA, sB);
  const int tcol = threadIdx.x % (BN/TN), trow = threadIdx.x / (BN/TN);
  #pragma unroll
  for (int i=0;i<TM;i++){
    int m = m0 + trow*TM + i;
    #pragma unroll
    for (int j=0;j<TN;j++){
      int n = n0 + tcol*TN + j;
      Y[m*256+n] = eluf(acc[i*TN+j] + bias[n]);
    }
  }
}

// max over E entities -> feat
__global__ void k_maxpool(const float* __restrict__ proc){
  int g = blockIdx.x;     // 0..2047
  int c = threadIdx.x;    // 0..255
  const float* p = proc + (size_t)g*NE*256 + c;
  float v = p[0];
  #pragma unroll
  for (int e=1;e<NE;e++) v = fmaxf(v, p[e*256]);
  g_feat[g*256+c] = v;
}

// build cat = [ma | feat | goals | 0pad]  (2048 x 528)
__global__ void k_pack(const float* __restrict__ ma, const float* __restrict__ goals){
  int idx = blockIdx.x*blockDim.x + threadIdx.x;
  if (idx >= MA_*KA) return;
  int m = idx / KA, c = idx % KA;
  float v;
  if      (c < 256) v = ma[m*256 + c];
  else if (c < 512) v = g_feat[m*256 + (c-256)];
  else if (c < 515) v = goals[m*3 + (c-512)];
  else              v = 0.f;
  g_cat[idx] = v;
}

// Action GRU: 4 strips (r,z,in,hn). grid (16, 8).
__global__ void __launch_bounds__(256) k_step_act(
    const float* __restrict__ ma, float* __restrict__ haout,
    const float* __restrict__ bih, const float* __restrict__ bhh)
{
  constexpr int BM=128, BN=128, BK=16, TM=8, TN=8;
  __shared__ __align__(16) float sA[BM*BK];
  __shared__ __align__(16) float sB[BK*BN];
  float acc[TM*TN];
  int m0 = blockIdx.x*BM;
  int n0 = blockIdx.y*32;
  gemm_core<BM,BN,BK,TM,TN,4,256>(g_cat, KA, g_WcatT, 1024, KA, m0, n0, acc, sA, sB);
  const int tcol = threadIdx.x % 16, trow = threadIdx.x / 16;
  #pragma unroll
  for (int i=0;i<TM;i++){
    int m = m0 + trow*TM + i;
    #pragma unroll
    for (int t=0;t<2;t++){
      int j = n0 + tcol*2 + t;
      float r = sigf(acc[i*8 + 0*2 + t] + bih[j]     + bhh[j]);
      float z = sigf(acc[i*8 + 1*2 + t] + bih[256+j] + bhh[256+j]);
      float n = tanhf(acc[i*8 + 2*2 + t] + bih[512+j] + r*(acc[i*8 + 3*2 + t] + bhh[512+j]));
      haout[m*256+j] = (1.f - z)*n + z*ma[m*256+j];
    }
  }
}

// movement head: out = tanh(m1 @ W2^T + b2) * 0.05 ; one warp per row
__global__ void k_move(const float* __restrict__ m1, const float* __restrict__ W2,
                       const float* __restrict__ b2, float* __restrict__ out){
  int warp = (blockIdx.x*blockDim.x + threadIdx.x) >> 5;
  int lane = threadIdx.x & 31;
  if (warp >= MA_) return;
  const float* x = m1 + (size_t)warp*256;
  float s0 = 0.f, s1 = 0.f;
  #pragma unroll
  for (int k=lane; k<256; k+=32){
    float xv = x[k];
    s0 = fmaf(xv, W2[k],       s0);
    s1 = fmaf(xv, W2[256 + k], s1);
  }
  #pragma unroll
  for (int o=16;o>0;o>>=1){
    s0 += __shfl_down_sync(0xffffffffu, s0, o);
    s1 += __shfl_down_sync(0xffffffffu, s1, o);
  }
  if (lane == 0){
    out[warp*2 + 0] = tanhf(s0 + b2[0]) * 0.05f;
    out[warp*2 + 1] = tanhf(s1 + b2[1]) * 0.05f;
  }
}

// ---------------- launch ----------------
extern "C" void kernel_launch(void* const* d_in, const int* in_sizes, int n_in,
                              void* d_out, int out_size){
  (void)in_sizes; (void)n_in; (void)out_size;
  const float* obs  = (const float*)d_in[0];
  const float* phys = (const float*)d_in[1];
  const float* goals= (const float*)d_in[2];
  const float* memp = (const float*)d_in[3];
  const float* mema = (const float*)d_in[4];
  const float* Wihp = (const float*)d_in[5];
  const float* Whhp = (const float*)d_in[6];
  const float* bihp = (const float*)d_in[7];
  const float* bhhp = (const float*)d_in[8];
  const float* Wfcp = (const float*)d_in[9];
  const float* bfcp = (const float*)d_in[10];
  const float* Wiha = (const float*)d_in[11];
  const float* Whha = (const float*)d_in[12];
  const float* biha = (const float*)d_in[13];
  const float* bhha = (const float*)d_in[14];
  const float* Wfca = (const float*)d_in[15];
  const float* bfca = (const float*)d_in[16];
  const float* Wm1  = (const float*)d_in[17];
  const float* bm1  = (const float*)d_in[18];
  const float* Wm2  = (const float*)d_in[19];
  const float* bm2  = (const float*)d_in[20];
  float* out = (float*)d_out;

  float *Pmp, *Pma, *Pproc, *Pproca, *Pm1;
  float *PWhhT, *PWcatT, *PWfcPT, *PWfcAT, *PWm1T;
  cudaGetSymbolAddress((void**)&Pmp,   g_mp);
  cudaGetSymbolAddress((void**)&Pma,   g_ma);
  cudaGetSymbolAddress((void**)&Pproc, g_proc);
  cudaGetSymbolAddress((void**)&Pproca,g_proca);
  cudaGetSymbolAddress((void**)&Pm1,   g_m1);
  cudaGetSymbolAddress((void**)&PWhhT, g_WhhT);
  cudaGetSymbolAddress((void**)&PWcatT,g_WcatT);
  cudaGetSymbolAddress((void**)&PWfcPT,g_WfcPT);
  cudaGetSymbolAddress((void**)&PWfcAT,g_WfcAT);
  cudaGetSymbolAddress((void**)&PWm1T, g_Wm1T);

  // init recurrent state (buffer 0)
  cudaMemcpyAsync(Pmp, memp, (size_t)MP *NH*sizeof(float), cudaMemcpyDeviceToDevice);
  cudaMemcpyAsync(Pma, mema, (size_t)MA_*NH*sizeof(float), cudaMemcpyDeviceToDevice);

  // precompute weight layouts + time-invariant gi
  k_transpose<<<(768*256+255)/256,256>>>(Whhp, PWhhT, 768, 256);
  k_transpose<<<(256*256+255)/256,256>>>(Wfcp, PWfcPT, 256, 256);
  k_transpose<<<(256*256+255)/256,256>>>(Wfca, PWfcAT, 256, 256);
  k_transpose<<<(256*256+255)/256,256>>>(Wm1,  PWm1T,  256, 256);
  k_wcat<<<(KA*1024+255)/256,256>>>(Wiha, Whha, PWcatT);
  k_giP<<<MP,256>>>(obs, phys, Wihp, bihp, bhhp);

  for (int t=0;t<NT;t++){
    int cur = t & 1, nxt = cur ^ 1;
    float* mpc = Pmp + (size_t)cur*MP *NH;
    float* mpn = Pmp + (size_t)nxt*MP *NH;
    float* mac = Pma + (size_t)cur*MA_*NH;
    float* man = Pma + (size_t)nxt*MA_*NH;

    k_step_phys<<<dim3(MP/128, 256/32), 256>>>(mpc, mpn, bhhp);
    k_fc_elu<128,128,8,8><<<dim3(MP/128, 256/128), 256>>>(mpn, PWfcPT, bfcp, Pproc);
    k_maxpool<<<MA_, 256>>>(Pproc);
    k_pack<<<(MA_*KA+255)/256, 256>>>(mac, goals);
    k_step_act<<<dim3(MA_/128, 256/32), 256>>>(mac, man, biha, bhha);
    k_fc_elu<64,64,4,4><<<dim3(MA_/64, 256/64), 256>>>(man, PWfcAT, bfca, Pproca);
    k_fc_elu<64,64,4,4><<<dim3(MA_/64, 256/64), 256>>>(Pproca, PWm1T, bm1, Pm1);
    k_move<<<MA_/8, 256>>>(Pm1, Wm2, bm2, out + (size_t)t*MA_*NMV);
  }
}

// round 14
// speedup vs baseline: 2.4500x; 2.4500x over previous
#include <cuda_runtime.h>
#include <cuda_bf16.h>
#include <math.h>

// Problem constants
#define NB   512
#define NA   4
#define NE   10
#define NH   256
#define NOBS 2
#define NPHY 3
#define NG   3
#define NMV  2
#define NT   10
#define MP   (NB*NA*NE)   // 20480 rows for physical module
#define MA_  (NB*NA)      // 2048 rows for action module
#define KA   544          // padded action inner dim (256 ma + 256 feat + 3 goals + 29 pad)

// ---------------- scratch (device globals; no runtime allocation) ----------------
__device__ __align__(16) float g_giP  [MP*768];     // precomputed x-side GRU terms (+biases folded)
__device__ __align__(16) float g_mp   [2*MP*NH];    // physical memory ping-pong
__device__ __align__(16) float g_ma   [2*MA_*NH];   // action memory ping-pong
__device__ __align__(16) float g_proc [MP*NH];
__device__ __align__(16) float g_feat [MA_*NH];
__device__ __align__(16) float g_cat  [MA_*KA];
__device__ __align__(16) float g_proca[MA_*NH];
__device__ __align__(16) float g_m1   [MA_*NH];

// packed bf16 hi/lo weight planes: layout [plane][n][k/2] (uint32 = bf16 pair (k,k+1))
__device__ __align__(16) unsigned g_pkWhh [2*768*128];
__device__ __align__(16) unsigned g_pkWfcP[2*256*128];
__device__ __align__(16) unsigned g_pkWfcA[2*256*128];
__device__ __align__(16) unsigned g_pkWm1 [2*256*128];
__device__ __align__(16) unsigned g_pkWcat[2*1024*272];

__device__ __forceinline__ float sigf(float x){ return 1.f/(1.f+expf(-x)); }
__device__ __forceinline__ float eluf(float x){ return x>0.f ? x : expm1f(x); }

// split two fp32 into packed bf16 hi / lo pairs (lo = round(a - hi))
__device__ __forceinline__ void split2(float a, float b, unsigned& hi, unsigned& lo){
  __nv_bfloat16 ah = __float2bfloat16_rn(a);
  __nv_bfloat16 bh = __float2bfloat16_rn(b);
  float ar = a - __bfloat162float(ah);
  float br = b - __bfloat162float(bh);
  __nv_bfloat16 al = __float2bfloat16_rn(ar);
  __nv_bfloat16 bl = __float2bfloat16_rn(br);
  hi = ((unsigned)__bfloat16_as_ushort(bh) << 16) | (unsigned)__bfloat16_as_ushort(ah);
  lo = ((unsigned)__bfloat16_as_ushort(bl) << 16) | (unsigned)__bfloat16_as_ushort(al);
}

// m16n8k16 bf16 mma, f32 accumulate
__device__ __forceinline__ void mma_bf16(float* c, unsigned a0, unsigned a1, unsigned a2, unsigned a3,
                                         unsigned b0, unsigned b1){
  asm volatile(
    "mma.sync.aligned.m16n8k16.row.col.f32.bf16.bf16.f32 "
    "{%0,%1,%2,%3}, {%4,%5,%6,%7}, {%8,%9}, {%0,%1,%2,%3};\n"
    : "+f"(c[0]), "+f"(c[1]), "+f"(c[2]), "+f"(c[3])
    : "r"(a0), "r"(a1), "r"(a2), "r"(a3), "r"(b0), "r"(b1));
}

// ---------------- smem staging ----------------
// A tile: BM x 32 fp32 -> hi/lo planes [m][k/2] padded row = 20 uint32
template<int BM>
__device__ __forceinline__ void stageA(const float* __restrict__ A, int lda, int m0, int k0,
                                       unsigned* sAhi, unsigned* sAlo){
  #pragma unroll
  for (int i = 0; i < BM/32; i++){
    int idx = threadIdx.x + i*256;           // BM*8 float4 total
    int m = idx >> 3, q = idx & 7;
    float4 v = *(const float4*)(A + (size_t)(m0+m)*lda + (k0 + q*4));
    unsigned h0,l0,h1,l1;
    split2(v.x, v.y, h0, l0);
    split2(v.z, v.w, h1, l1);
    int base = m*20 + q*2;
    sAhi[base] = h0; sAhi[base+1] = h1;
    sAlo[base] = l0; sAlo[base+1] = l1;
  }
}

// B tile from packed weights: ROWS rows of 16 uint32 per plane, strip width SW
// (local row r -> source n = (r/SW)*256 + n0 + r%SW)
template<int ROWS, int SW>
__device__ __forceinline__ void stageB(const unsigned* __restrict__ pk, int Nk2, int planeStride,
                                       int n0, int k0, unsigned* sBhi, unsigned* sBlo){
  #pragma unroll
  for (int i = 0; i < (ROWS*8)/256; i++){
    int idx = threadIdx.x + i*256;           // ROWS*4 uint4 per plane, 2 planes
    int plane = (idx >= ROWS*4) ? 1 : 0;
    int rem = idx - plane*ROWS*4;
    int r = rem >> 2, c4 = rem & 3;
    int strip = r / SW, j = r % SW;
    int srcn = strip*256 + n0 + j;
    uint4 v = *(const uint4*)(pk + (size_t)plane*planeStride + (size_t)srcn*Nk2 + (k0>>1) + c4*4);
    unsigned* dst = (plane ? sBlo : sBhi) + r*20 + c4*4;
    *(uint4*)dst = v;
  }
}

// ---------------- precompute kernels ----------------
__global__ void k_packW(const float* __restrict__ W, unsigned* __restrict__ pk, int N, int K){
  int idx = blockIdx.x*blockDim.x + threadIdx.x;
  int K2 = K >> 1;
  int half = N*K2;
  if (idx >= half) return;
  int n = idx / K2, kq = idx % K2;
  unsigned hi, lo;
  split2(W[(size_t)n*K + 2*kq], W[(size_t)n*K + 2*kq + 1], hi, lo);
  pk[idx] = hi; pk[half + idx] = lo;
}

// fused action weight value: rows n in [0,1024), k in [0,544)
//  strip 0 (r): k<256 -> Whh[j][k]; 256<=k<515 -> Wih[j][k-256]
//  strip 1 (z): same with out row 256+j
//  strip 2 (in): only x part; strip 3 (hn): only ma part
__device__ __forceinline__ float wcat_val(const float* Wih, const float* Whh, int n, int k){
  int strip = n >> 8, j = n & 255;
  if (strip < 2){
    int o = strip*256 + j;
    if (k < 256)      return Whh[o*256 + k];
    else if (k < 515) return Wih[o*259 + (k-256)];
    return 0.f;
  } else if (strip == 2){
    if (k >= 256 && k < 515) return Wih[(512+j)*259 + (k-256)];
    return 0.f;
  } else {
    if (k < 256) return Whh[(512+j)*256 + k];
    return 0.f;
  }
}
__global__ void k_packWcat(const float* __restrict__ Wih, const float* __restrict__ Whh,
                           unsigned* __restrict__ pk){
  int idx = blockIdx.x*blockDim.x + threadIdx.x;
  if (idx >= 1024*272) return;
  int n = idx / 272, kq = idx % 272;
  float a = wcat_val(Wih, Whh, n, 2*kq);
  float b = wcat_val(Wih, Whh, n, 2*kq + 1);
  unsigned hi, lo;
  split2(a, b, hi, lo);
  pk[idx] = hi; pk[1024*272 + idx] = lo;
}

// g_giP[m*768 + g*256 + j] = x_p[m] . W_ih_p[g*256+j] + b_ih (+ b_hh for r,z)
__global__ void k_giP(const float* __restrict__ obs, const float* __restrict__ phys,
                      const float* __restrict__ Wih, const float* __restrict__ bih,
                      const float* __restrict__ bhh){
  int m = blockIdx.x, j = threadIdx.x;
  int b = m / (NA*NE);
  int e = m % NE;
  float x0 = obs[m*NOBS+0], x1 = obs[m*NOBS+1];
  const float* p = phys + (b*NE + e)*NPHY;
  float x2 = p[0], x3 = p[1], x4 = p[2];
  #pragma unroll
  for (int g=0; g<3; g++){
    int o = g*256 + j;
    const float* w = Wih + o*5;
    float v = x0*w[0] + x1*w[1] + x2*w[2] + x3*w[3] + x4*w[4] + bih[o];
    if (g < 2) v += bhh[o];
    g_giP[(size_t)m*768 + o] = v;
  }
}

// ---------------- per-step mma kernels ----------------
// Physical GRU: BM=128, 32 h-cols/block, 3 strips (r,z,hn). 8 warps, warp-tile 16x96.
__global__ void __launch_bounds__(256) k_step_phys(
    const float* __restrict__ mp, float* __restrict__ hout, const float* __restrict__ bhh)
{
  __shared__ __align__(16) unsigned sAhi[128*20], sAlo[128*20];
  __shared__ __align__(16) unsigned sBhi[96*20],  sBlo[96*20];
  const int m0 = blockIdx.x*128, n0 = blockIdx.y*32;
  const int lane = threadIdx.x & 31, w = threadIdx.x >> 5;
  float acc[3][4][4];
  #pragma unroll
  for (int s=0;s<3;s++)
    #pragma unroll
    for (int f=0;f<4;f++)
      #pragma unroll
      for (int c=0;c<4;c++) acc[s][f][c]=0.f;

  for (int k0 = 0; k0 < 256; k0 += 32){
    stageA<128>(mp, 256, m0, k0, sAhi, sAlo);
    stageB<96,32>(g_pkWhh, 128, 768*128, n0, k0, sBhi, sBlo);
    __syncthreads();
    const int arow = (w*16 + (lane>>2))*20;
    #pragma unroll
    for (int ks=0; ks<2; ks++){
      int kb = ks*8 + (lane&3);
      unsigned ah0=sAhi[arow+kb], ah1=sAhi[arow+160+kb], ah2=sAhi[arow+kb+4], ah3=sAhi[arow+160+kb+4];
      unsigned al0=sAlo[arow+kb], al1=sAlo[arow+160+kb], al2=sAlo[arow+kb+4], al3=sAlo[arow+160+kb+4];
      #pragma unroll
      for (int s=0;s<3;s++){
        #pragma unroll
        for (int f=0;f<4;f++){
          int brow = (s*32 + f*8 + (lane>>2))*20;
          unsigned bh0=sBhi[brow+kb], bh1=sBhi[brow+kb+4];
          unsigned bl0=sBlo[brow+kb], bl1=sBlo[brow+kb+4];
          mma_bf16(acc[s][f], ah0,ah1,ah2,ah3, bh0,bh1);
          mma_bf16(acc[s][f], ah0,ah1,ah2,ah3, bl0,bl1);
          mma_bf16(acc[s][f], al0,al1,al2,al3, bh0,bh1);
        }
      }
    }
    __syncthreads();
  }
  // fused GRU epilogue
  int mb = m0 + w*16 + (lane>>2);
  int jb = n0 + 2*(lane&3);
  #pragma unroll
  for (int mr=0; mr<2; mr++){
    int m = mb + mr*8;
    const float* gi = g_giP + (size_t)m*768;
    #pragma unroll
    for (int f=0; f<4; f++){
      #pragma unroll
      for (int c=0; c<2; c++){
        int j = jb + f*8 + c;
        int ci = mr*2 + c;
        float r = sigf(acc[0][f][ci] + gi[j]);
        float z = sigf(acc[1][f][ci] + gi[256+j]);
        float n = tanhf(gi[512+j] + r*(acc[2][f][ci] + bhh[512+j]));
        hout[(size_t)m*256 + j] = (1.f - z)*n + z*mp[(size_t)m*256 + j];
      }
    }
  }
}

// FC + ELU: BM=64, BN=64, warps 2x4, warp-tile 32x16. K=256, N=256.
__global__ void __launch_bounds__(256) k_fc_elu(
    const float* __restrict__ X, const unsigned* __restrict__ pk,
    const float* __restrict__ bias, float* __restrict__ Y)
{
  __shared__ __align__(16) unsigned sAhi[64*20], sAlo[64*20];
  __shared__ __align__(16) unsigned sBhi[64*20], sBlo[64*20];
  const int m0 = blockIdx.x*64, n0 = blockIdx.y*64;
  const int lane = threadIdx.x & 31, w = threadIdx.x >> 5;
  const int wm = (w>>2)*32, wn = (w&3)*16;
  float acc[2][2][4];
  #pragma unroll
  for (int a=0;a<2;a++)
    #pragma unroll
    for (int b=0;b<2;b++)
      #pragma unroll
      for (int c=0;c<4;c++) acc[a][b][c]=0.f;

  for (int k0 = 0; k0 < 256; k0 += 32){
    stageA<64>(X, 256, m0, k0, sAhi, sAlo);
    stageB<64,64>(pk, 128, 256*128, n0, k0, sBhi, sBlo);
    __syncthreads();
    #pragma unroll
    for (int ks=0; ks<2; ks++){
      int kb = ks*8 + (lane&3);
      unsigned ah[2][4], al[2][4];
      #pragma unroll
      for (int mf=0; mf<2; mf++){
        int ar = (wm + mf*16 + (lane>>2))*20;
        ah[mf][0]=sAhi[ar+kb]; ah[mf][1]=sAhi[ar+160+kb]; ah[mf][2]=sAhi[ar+kb+4]; ah[mf][3]=sAhi[ar+160+kb+4];
        al[mf][0]=sAlo[ar+kb]; al[mf][1]=sAlo[ar+160+kb]; al[mf][2]=sAlo[ar+kb+4]; al[mf][3]=sAlo[ar+160+kb+4];
      }
      #pragma unroll
      for (int nf=0; nf<2; nf++){
        int br = (wn + nf*8 + (lane>>2))*20;
        unsigned bh0=sBhi[br+kb], bh1=sBhi[br+kb+4];
        unsigned bl0=sBlo[br+kb], bl1=sBlo[br+kb+4];
        #pragma unroll
        for (int mf=0; mf<2; mf++){
          mma_bf16(acc[mf][nf], ah[mf][0],ah[mf][1],ah[mf][2],ah[mf][3], bh0,bh1);
          mma_bf16(acc[mf][nf], ah[mf][0],ah[mf][1],ah[mf][2],ah[mf][3], bl0,bl1);
          mma_bf16(acc[mf][nf], al[mf][0],al[mf][1],al[mf][2],al[mf][3], bh0,bh1);
        }
      }
    }
    __syncthreads();
  }
  int mb = m0 + wm + (lane>>2);
  int nb = n0 + wn + 2*(lane&3);
  #pragma unroll
  for (int mf=0; mf<2; mf++)
    #pragma unroll
    for (int mr=0; mr<2; mr++){
      int m = mb + mf*16 + mr*8;
      #pragma unroll
      for (int nf=0; nf<2; nf++)
        #pragma unroll
        for (int c=0; c<2; c++){
          int nn = nb + nf*8 + c;
          Y[(size_t)m*256 + nn] = eluf(acc[mf][nf][mr*2+c] + bias[nn]);
        }
    }
}

// Action GRU: BM=128, 16 h-cols/block, 4 strips (r,z,in,hn). K=544. warp-tile 16x64.
__global__ void __launch_bounds__(256) k_step_act(
    const float* __restrict__ ma, float* __restrict__ haout,
    const float* __restrict__ bih, const float* __restrict__ bhh)
{
  __shared__ __align__(16) unsigned sAhi[128*20], sAlo[128*20];
  __shared__ __align__(16) unsigned sBhi[64*20],  sBlo[64*20];
  const int m0 = blockIdx.x*128, n0 = blockIdx.y*16;
  const int lane = threadIdx.x & 31, w = threadIdx.x >> 5;
  float acc[4][2][4];
  #pragma unroll
  for (int s=0;s<4;s++)
    #pragma unroll
    for (int f=0;f<2;f++)
      #pragma unroll
      for (int c=0;c<4;c++) acc[s][f][c]=0.f;

  for (int k0 = 0; k0 < KA; k0 += 32){
    stageA<128>(g_cat, KA, m0, k0, sAhi, sAlo);
    stageB<64,16>(g_pkWcat, 272, 1024*272, n0, k0, sBhi, sBlo);
    __syncthreads();
    const int arow = (w*16 + (lane>>2))*20;
    #pragma unroll
    for (int ks=0; ks<2; ks++){
      int kb = ks*8 + (lane&3);
      unsigned ah0=sAhi[arow+kb], ah1=sAhi[arow+160+kb], ah2=sAhi[arow+kb+4], ah3=sAhi[arow+160+kb+4];
      unsigned al0=sAlo[arow+kb], al1=sAlo[arow+160+kb], al2=sAlo[arow+kb+4], al3=sAlo[arow+160+kb+4];
      #pragma unroll
      for (int s=0;s<4;s++){
        #pragma unroll
        for (int f=0;f<2;f++){
          int brow = (s*16 + f*8 + (lane>>2))*20;
          unsigned bh0=sBhi[brow+kb], bh1=sBhi[brow+kb+4];
          unsigned bl0=sBlo[brow+kb], bl1=sBlo[brow+kb+4];
          mma_bf16(acc[s][f], ah0,ah1,ah2,ah3, bh0,bh1);
          mma_bf16(acc[s][f], ah0,ah1,ah2,ah3, bl0,bl1);
          mma_bf16(acc[s][f], al0,al1,al2,al3, bh0,bh1);
        }
      }
    }
    __syncthreads();
  }
  int mb = m0 + w*16 + (lane>>2);
  int jb = n0 + 2*(lane&3);
  #pragma unroll
  for (int mr=0; mr<2; mr++){
    int m = mb + mr*8;
    #pragma unroll
    for (int f=0; f<2; f++){
      #pragma unroll
      for (int c=0; c<2; c++){
        int j = jb + f*8 + c;
        int ci = mr*2 + c;
        float r = sigf(acc[0][f][ci] + bih[j]     + bhh[j]);
        float z = sigf(acc[1][f][ci] + bih[256+j] + bhh[256+j]);
        float n = tanhf(acc[2][f][ci] + bih[512+j] + r*(acc[3][f][ci] + bhh[512+j]));
        haout[(size_t)m*256 + j] = (1.f - z)*n + z*ma[(size_t)m*256 + j];
      }
    }
  }
}

// ---------------- small fp32 helpers ----------------
// max over E entities -> feat
__global__ void k_maxpool(const float* __restrict__ proc){
  int g = blockIdx.x;     // 0..2047
  int c = threadIdx.x;    // 0..255
  const float* p = proc + (size_t)g*NE*256 + c;
  float v = p[0];
  #pragma unroll
  for (int e=1;e<NE;e++) v = fmaxf(v, p[e*256]);
  g_feat[g*256+c] = v;
}

// build cat = [ma | feat | goals | 0pad]  (2048 x 544)
__global__ void k_pack(const float* __restrict__ ma, const float* __restrict__ goals){
  int idx = blockIdx.x*blockDim.x + threadIdx.x;
  if (idx >= MA_*KA) return;
  int m = idx / KA, c = idx % KA;
  float v;
  if      (c < 256) v = ma[m*256 + c];
  else if (c < 512) v = g_feat[m*256 + (c-256)];
  else if (c < 515) v = goals[m*3 + (c-512)];
  else              v = 0.f;
  g_cat[idx] = v;
}

// movement head: out = tanh(m1 @ W2^T + b2) * 0.05 ; one warp per row
__global__ void k_move(const float* __restrict__ m1, const float* __restrict__ W2,
                       const float* __restrict__ b2, float* __restrict__ out){
  int warp = (blockIdx.x*blockDim.x + threadIdx.x) >> 5;
  int lane = threadIdx.x & 31;
  if (warp >= MA_) return;
  const float* x = m1 + (size_t)warp*256;
  float s0 = 0.f, s1 = 0.f;
  #pragma unroll
  for (int k=lane; k<256; k+=32){
    float xv = x[k];
    s0 = fmaf(xv, W2[k],       s0);
    s1 = fmaf(xv, W2[256 + k], s1);
  }
  #pragma unroll
  for (int o=16;o>0;o>>=1){
    s0 += __shfl_down_sync(0xffffffffu, s0, o);
    s1 += __shfl_down_sync(0xffffffffu, s1, o);
  }
  if (lane == 0){
    out[warp*2 + 0] = tanhf(s0 + b2[0]) * 0.05f;
    out[warp*2 + 1] = tanhf(s1 + b2[1]) * 0.05f;
  }
}

// ---------------- launch ----------------
extern "C" void kernel_launch(void* const* d_in, const int* in_sizes, int n_in,
                              void* d_out, int out_size){
  (void)in_sizes; (void)n_in; (void)out_size;
  const float* obs  = (const float*)d_in[0];
  const float* phys = (const float*)d_in[1];
  const float* goals= (const float*)d_in[2];
  const float* memp = (const float*)d_in[3];
  const float* mema = (const float*)d_in[4];
  const float* Wihp = (const float*)d_in[5];
  const float* Whhp = (const float*)d_in[6];
  const float* bihp = (const float*)d_in[7];
  const float* bhhp = (const float*)d_in[8];
  const float* Wfcp = (const float*)d_in[9];
  const float* bfcp = (const float*)d_in[10];
  const float* Wiha = (const float*)d_in[11];
  const float* Whha = (const float*)d_in[12];
  const float* biha = (const float*)d_in[13];
  const float* bhha = (const float*)d_in[14];
  const float* Wfca = (const float*)d_in[15];
  const float* bfca = (const float*)d_in[16];
  const float* Wm1  = (const float*)d_in[17];
  const float* bm1  = (const float*)d_in[18];
  const float* Wm2  = (const float*)d_in[19];
  const float* bm2  = (const float*)d_in[20];
  float* out = (float*)d_out;

  float *Pmp, *Pma, *Pproc, *Pproca, *Pm1;
  unsigned *PpkWhh, *PpkWfcP, *PpkWfcA, *PpkWm1, *PpkWcat;
  cudaGetSymbolAddress((void**)&Pmp,    g_mp);
  cudaGetSymbolAddress((void**)&Pma,    g_ma);
  cudaGetSymbolAddress((void**)&Pproc,  g_proc);
  cudaGetSymbolAddress((void**)&Pproca, g_proca);
  cudaGetSymbolAddress((void**)&Pm1,    g_m1);
  cudaGetSymbolAddress((void**)&PpkWhh, g_pkWhh);
  cudaGetSymbolAddress((void**)&PpkWfcP,g_pkWfcP);
  cudaGetSymbolAddress((void**)&PpkWfcA,g_pkWfcA);
  cudaGetSymbolAddress((void**)&PpkWm1, g_pkWm1);
  cudaGetSymbolAddress((void**)&PpkWcat,g_pkWcat);

  // init recurrent state (buffer 0)
  cudaMemcpyAsync(Pmp, memp, (size_t)MP *NH*sizeof(float), cudaMemcpyDeviceToDevice);
  cudaMemcpyAsync(Pma, mema, (size_t)MA_*NH*sizeof(float), cudaMemcpyDeviceToDevice);

  // precompute packed bf16 hi/lo weights + time-invariant gi
  k_packW  <<<(768*128+255)/256, 256>>>(Whhp, PpkWhh, 768, 256);
  k_packW  <<<(256*128+255)/256, 256>>>(Wfcp, PpkWfcP, 256, 256);
  k_packW  <<<(256*128+255)/256, 256>>>(Wfca, PpkWfcA, 256, 256);
  k_packW  <<<(256*128+255)/256, 256>>>(Wm1,  PpkWm1,  256, 256);
  k_packWcat<<<(1024*272+255)/256,256>>>(Wiha, Whha, PpkWcat);
  k_giP<<<MP,256>>>(obs, phys, Wihp, bihp, bhhp);

  for (int t=0;t<NT;t++){
    int cur = t & 1, nxt = cur ^ 1;
    float* mpc = Pmp + (size_t)cur*MP *NH;
    float* mpn = Pmp + (size_t)nxt*MP *NH;
    float* mac = Pma + (size_t)cur*MA_*NH;
    float* man = Pma + (size_t)nxt*MA_*NH;

    k_step_phys<<<dim3(MP/128, 8),  256>>>(mpc, mpn, bhhp);
    k_fc_elu   <<<dim3(MP/64,  4),  256>>>(mpn, PpkWfcP, bfcp, Pproc);
    k_maxpool  <<<MA_, 256>>>(Pproc);
    k_pack     <<<(MA_*KA+255)/256, 256>>>(mac, goals);
    k_step_act <<<dim3(MA_/128, 16),256>>>(mac, man, biha, bhha);
    k_fc_elu   <<<dim3(MA_/64, 4),  256>>>(man, PpkWfcA, bfca, Pproca);
    k_fc_elu   <<<dim3(MA_/64, 4),  256>>>(Pproca, PpkWm1, bm1, Pm1);
    k_move     <<<MA_/8, 256>>>(Pm1, Wm2, bm2, out + (size_t)t*MA_*NMV);
  }
}

// round 15
// speedup vs baseline: 2.4670x; 1.0069x over previous
#include <cuda_runtime.h>
#include <cuda_bf16.h>
#include <math.h>

// Problem constants
#define NB   512
#define NA   4
#define NE   10
#define NH   256
#define NOBS 2
#define NPHY 3
#define NG   3
#define NMV  2
#define NT   10
#define MP   (NB*NA*NE)   // 20480 rows for physical module
#define MA_  (NB*NA)      // 2048 rows for action module
#define KA   544          // padded action inner dim
#define K2FG 144          // (KA-256)/2 : packed feat(128)+goals/pad(16)

// ---------------- scratch (device globals; no runtime allocation) ----------------
__device__ __align__(16) float g_giP [MP*768];
__device__ __align__(16) float g_mp  [2*MP*NH];     // fp32 physical memory ping-pong
__device__ __align__(16) float g_ma  [2*MA_*NH];    // fp32 action memory ping-pong
__device__ __align__(16) float g_proc[MP*NH];
__device__ __align__(16) float g_m1  [MA_*NH];

// packed bf16 hi/lo activation planes: [buf][plane][m][K/2] flattened
__device__ __align__(16) unsigned g_pkMp   [2*2*MP*128];
__device__ __align__(16) unsigned g_pkMan  [2*2*MA_*128];
__device__ __align__(16) unsigned g_pkProca[2*MA_*128];
__device__ __align__(16) unsigned g_catFG  [2*MA_*K2FG];  // feat+goals part of cat (k 256..543)

// packed bf16 hi/lo weight planes: [plane][n][K/2]
__device__ __align__(16) unsigned g_pkWhh [2*768*128];
__device__ __align__(16) unsigned g_pkWfcP[2*256*128];
__device__ __align__(16) unsigned g_pkWfcA[2*256*128];
__device__ __align__(16) unsigned g_pkWm1 [2*256*128];
__device__ __align__(16) unsigned g_pkWcat[2*1024*272];

__device__ __forceinline__ float sigf(float x){ return 1.f/(1.f+expf(-x)); }
__device__ __forceinline__ float eluf(float x){ return x>0.f ? x : expm1f(x); }

__device__ __forceinline__ void split2(float a, float b, unsigned& hi, unsigned& lo){
  __nv_bfloat16 ah = __float2bfloat16_rn(a);
  __nv_bfloat16 bh = __float2bfloat16_rn(b);
  float ar = a - __bfloat162float(ah);
  float br = b - __bfloat162float(bh);
  __nv_bfloat16 al = __float2bfloat16_rn(ar);
  __nv_bfloat16 bl = __float2bfloat16_rn(br);
  hi = ((unsigned)__bfloat16_as_ushort(bh) << 16) | (unsigned)__bfloat16_as_ushort(ah);
  lo = ((unsigned)__bfloat16_as_ushort(bl) << 16) | (unsigned)__bfloat16_as_ushort(al);
}

__device__ __forceinline__ void mma_bf16(float* c, unsigned a0, unsigned a1, unsigned a2, unsigned a3,
                                         unsigned b0, unsigned b1){
  asm volatile(
    "mma.sync.aligned.m16n8k16.row.col.f32.bf16.bf16.f32 "
    "{%0,%1,%2,%3}, {%4,%5,%6,%7}, {%8,%9}, {%0,%1,%2,%3};\n"
    : "+f"(c[0]), "+f"(c[1]), "+f"(c[2]), "+f"(c[3])
    : "r"(a0), "r"(a1), "r"(a2), "r"(a3), "r"(b0), "r"(b1));
}

// ---------------- cp.async helpers ----------------
__device__ __forceinline__ void cp16(unsigned* s, const unsigned* g){
  unsigned sa = (unsigned)__cvta_generic_to_shared(s);
  asm volatile("cp.async.cg.shared.global [%0], [%1], 16;\n" :: "r"(sa), "l"(g));
}
__device__ __forceinline__ void cp_commit(){ asm volatile("cp.async.commit_group;\n" ::: "memory"); }
template<int N> __device__ __forceinline__ void cp_wait(){
  asm volatile("cp.async.wait_group %0;\n" :: "n"(N) : "memory");
}

// ---------------- smem staging (packed source; BK=16; row = 8 payload + 4 pad uint32) ----------------
// A tile: BM rows from packed planes
template<int BM>
__device__ __forceinline__ void stageApk(const unsigned* __restrict__ hi, const unsigned* __restrict__ lo,
                                         int K2, int m0, int k0, unsigned* sAhi, unsigned* sAlo){
  #pragma unroll
  for (int i = 0; i < BM/64; i++){
    int idx = threadIdx.x + i*256;           // BM*4 chunks of 16B
    int row = idx >> 2, p = (idx >> 1) & 1, c = idx & 1;
    const unsigned* src = (p ? lo : hi) + (size_t)(m0+row)*K2 + (k0>>1) + c*4;
    unsigned* dst = (p ? sAlo : sAhi) + row*12 + c*4;
    cp16(dst, src);
  }
}

// B tile: ROWS weight rows, strip width SW (local row r -> src n = (r/SW)*256 + n0 + r%SW)
template<int ROWS, int SW>
__device__ __forceinline__ void stageBpk(const unsigned* __restrict__ pk, int K2, int planeStride,
                                         int n0, int k0, unsigned* sBhi, unsigned* sBlo){
  #pragma unroll
  for (int i = 0; i < (ROWS*4 + 255)/256; i++){
    int idx = threadIdx.x + i*256;
    if ((ROWS*4) % 256 != 0 && idx >= ROWS*4) break;
    int r = idx >> 2, p = (idx >> 1) & 1, c = idx & 1;
    int srcn = (r/SW)*256 + n0 + (r%SW);
    const unsigned* src = pk + (size_t)p*planeStride + (size_t)srcn*K2 + (k0>>1) + c*4;
    unsigned* dst = (p ? sBlo : sBhi) + r*12 + c*4;
    cp16(dst, src);
  }
}

// A staging for action GRU: k<256 from pkMan, k>=256 from catFG
__device__ __forceinline__ void stageA_act(const unsigned* __restrict__ maHi, const unsigned* __restrict__ maLo,
                                           const unsigned* __restrict__ fgHi, const unsigned* __restrict__ fgLo,
                                           int m0, int k0, unsigned* sAhi, unsigned* sAlo){
  #pragma unroll
  for (int i = 0; i < 2; i++){
    int idx = threadIdx.x + i*256;           // 512 chunks
    int row = idx >> 2, p = (idx >> 1) & 1, c = idx & 1;
    const unsigned* src;
    if (k0 < 256) src = (p ? maLo : maHi) + (size_t)(m0+row)*128  + (k0>>1)       + c*4;
    else          src = (p ? fgLo : fgHi) + (size_t)(m0+row)*K2FG + ((k0-256)>>1) + c*4;
    unsigned* dst = (p ? sAlo : sAhi) + row*12 + c*4;
    cp16(dst, src);
  }
}

// ---------------- precompute kernels ----------------
__global__ void k_packW(const float* __restrict__ W, unsigned* __restrict__ pk, int N, int K){
  int idx = blockIdx.x*blockDim.x + threadIdx.x;
  int K2 = K >> 1;
  int half = N*K2;
  if (idx >= half) return;
  int n = idx / K2, kq = idx % K2;
  unsigned hi, lo;
  split2(W[(size_t)n*K + 2*kq], W[(size_t)n*K + 2*kq + 1], hi, lo);
  pk[idx] = hi; pk[half + idx] = lo;
}

__device__ __forceinline__ float wcat_val(const float* Wih, const float* Whh, int n, int k){
  int strip = n >> 8, j = n & 255;
  if (strip < 2){
    int o = strip*256 + j;
    if (k < 256)      return Whh[o*256 + k];
    else if (k < 515) return Wih[o*259 + (k-256)];
    return 0.f;
  } else if (strip == 2){
    if (k >= 256 && k < 515) return Wih[(512+j)*259 + (k-256)];
    return 0.f;
  } else {
    if (k < 256) return Whh[(512+j)*256 + k];
    return 0.f;
  }
}
__global__ void k_packWcat(const float* __restrict__ Wih, const float* __restrict__ Whh,
                           unsigned* __restrict__ pk){
  int idx = blockIdx.x*blockDim.x + threadIdx.x;
  if (idx >= 1024*272) return;
  int n = idx / 272, kq = idx % 272;
  unsigned hi, lo;
  split2(wcat_val(Wih, Whh, n, 2*kq), wcat_val(Wih, Whh, n, 2*kq+1), hi, lo);
  pk[idx] = hi; pk[1024*272 + idx] = lo;
}

// pack an [M][2*npairs_per_row] fp32 matrix linearly into hi/lo planes
__global__ void k_packAct(const float* __restrict__ X, unsigned* __restrict__ hi,
                          unsigned* __restrict__ lo, int npairs){
  int idx = blockIdx.x*blockDim.x + threadIdx.x;
  if (idx >= npairs) return;
  unsigned h, l;
  split2(X[2*idx], X[2*idx+1], h, l);
  hi[idx] = h; lo[idx] = l;
}

// pack goals (+zero pad) into catFG cols 128..143 (k 512..543) — once; goals constant over t
__global__ void k_packGoals(const float* __restrict__ goals){
  int idx = blockIdx.x*blockDim.x + threadIdx.x;
  if (idx >= MA_*16) return;
  int m = idx >> 4, q = idx & 15;
  float a = (2*q   < 3) ? goals[m*3 + 2*q]   : 0.f;
  float b = (2*q+1 < 3) ? goals[m*3 + 2*q+1] : 0.f;
  unsigned h, l;
  split2(a, b, h, l);
  g_catFG[(size_t)m*K2FG + 128 + q] = h;
  g_catFG[(size_t)MA_*K2FG + (size_t)m*K2FG + 128 + q] = l;
}

// g_giP[m*768 + g*256 + j] = x_p[m] . W_ih_p[g*256+j] + b_ih (+ b_hh for r,z)
__global__ void k_giP(const float* __restrict__ obs, const float* __restrict__ phys,
                      const float* __restrict__ Wih, const float* __restrict__ bih,
                      const float* __restrict__ bhh){
  int m = blockIdx.x, j = threadIdx.x;
  int b = m / (NA*NE);
  int e = m % NE;
  float x0 = obs[m*NOBS+0], x1 = obs[m*NOBS+1];
  const float* p = phys + (b*NE + e)*NPHY;
  float x2 = p[0], x3 = p[1], x4 = p[2];
  #pragma unroll
  for (int g=0; g<3; g++){
    int o = g*256 + j;
    const float* w = Wih + o*5;
    float v = x0*w[0] + x1*w[1] + x2*w[2] + x3*w[3] + x4*w[4] + bih[o];
    if (g < 2) v += bhh[o];
    g_giP[(size_t)m*768 + o] = v;
  }
}

// ---------------- per-step mma kernels (2-stage cp.async pipeline, BK=16) ----------------
// Physical GRU: BM=128, 32 h-cols/block, 3 strips (r,z,hn). 8 warps, warp-tile 16x96.
__global__ void __launch_bounds__(256) k_step_phys(
    const float* __restrict__ mp, float* __restrict__ hout,
    const unsigned* __restrict__ aHi, const unsigned* __restrict__ aLo,
    unsigned* __restrict__ oHi, unsigned* __restrict__ oLo,
    const float* __restrict__ bhh)
{
  __shared__ __align__(16) unsigned sAhi[2][128*12], sAlo[2][128*12];
  __shared__ __align__(16) unsigned sBhi[2][96*12],  sBlo[2][96*12];
  const int m0 = blockIdx.x*128, n0 = blockIdx.y*32;
  const int lane = threadIdx.x & 31, w = threadIdx.x >> 5;
  float acc[3][4][4];
  #pragma unroll
  for (int s=0;s<3;s++)
    #pragma unroll
    for (int f=0;f<4;f++)
      #pragma unroll
      for (int c=0;c<4;c++) acc[s][f][c]=0.f;

  constexpr int KT = 16;
  stageApk<128>(aHi, aLo, 128, m0, 0, sAhi[0], sAlo[0]);
  stageBpk<96,32>(g_pkWhh, 128, 768*128, n0, 0, sBhi[0], sBlo[0]);
  cp_commit();
  for (int kt=0; kt<KT; ++kt){
    if (kt+1 < KT){
      stageApk<128>(aHi, aLo, 128, m0, (kt+1)*16, sAhi[(kt+1)&1], sAlo[(kt+1)&1]);
      stageBpk<96,32>(g_pkWhh, 128, 768*128, n0, (kt+1)*16, sBhi[(kt+1)&1], sBlo[(kt+1)&1]);
      cp_commit();
      cp_wait<1>();
    } else {
      cp_wait<0>();
    }
    __syncthreads();
    const int b = kt & 1;
    const int arow = (w*16 + (lane>>2))*12;
    const int kb = lane & 3;
    unsigned ah0=sAhi[b][arow+kb], ah1=sAhi[b][arow+96+kb], ah2=sAhi[b][arow+kb+4], ah3=sAhi[b][arow+96+kb+4];
    unsigned al0=sAlo[b][arow+kb], al1=sAlo[b][arow+96+kb], al2=sAlo[b][arow+kb+4], al3=sAlo[b][arow+96+kb+4];
    #pragma unroll
    for (int s=0;s<3;s++){
      #pragma unroll
      for (int f=0;f<4;f++){
        int brow = (s*32 + f*8 + (lane>>2))*12;
        unsigned bh0=sBhi[b][brow+kb], bh1=sBhi[b][brow+kb+4];
        unsigned bl0=sBlo[b][brow+kb], bl1=sBlo[b][brow+kb+4];
        mma_bf16(acc[s][f], ah0,ah1,ah2,ah3, bh0,bh1);
        mma_bf16(acc[s][f], ah0,ah1,ah2,ah3, bl0,bl1);
        mma_bf16(acc[s][f], al0,al1,al2,al3, bh0,bh1);
      }
    }
    __syncthreads();
  }
  // fused GRU epilogue + packed output planes
  int mb = m0 + w*16 + (lane>>2);
  int jb0 = 2*(lane&3);
  #pragma unroll
  for (int mr=0; mr<2; mr++){
    int m = mb + mr*8;
    const float* gi = g_giP + (size_t)m*768;
    #pragma unroll
    for (int f=0; f<4; f++){
      float o[2];
      #pragma unroll
      for (int c=0; c<2; c++){
        int j = n0 + jb0 + f*8 + c;
        int ci = mr*2 + c;
        float r = sigf(acc[0][f][ci] + gi[j]);
        float z = sigf(acc[1][f][ci] + gi[256+j]);
        float n = tanhf(gi[512+j] + r*(acc[2][f][ci] + bhh[512+j]));
        o[c] = (1.f - z)*n + z*mp[(size_t)m*256 + j];
      }
      int j0 = n0 + jb0 + f*8;
      *(float2*)(hout + (size_t)m*256 + j0) = make_float2(o[0], o[1]);
      unsigned hi, lo;
      split2(o[0], o[1], hi, lo);
      oHi[(size_t)m*128 + (j0>>1)] = hi;
      oLo[(size_t)m*128 + (j0>>1)] = lo;
    }
  }
}

// FC + ELU: BM=64, BN=64, warps 2x4, warp-tile 32x16. K=256.
// MODE 0: write fp32 Y only.  MODE 1: write packed planes only.
template<int MODE>
__global__ void __launch_bounds__(256) k_fc_elu(
    const unsigned* __restrict__ aHi, const unsigned* __restrict__ aLo,
    const unsigned* __restrict__ pkW, const float* __restrict__ bias,
    float* __restrict__ Y, unsigned* __restrict__ yHi, unsigned* __restrict__ yLo)
{
  __shared__ __align__(16) unsigned sAhi[2][64*12], sAlo[2][64*12];
  __shared__ __align__(16) unsigned sBhi[2][64*12], sBlo[2][64*12];
  const int m0 = blockIdx.x*64, n0 = blockIdx.y*64;
  const int lane = threadIdx.x & 31, w = threadIdx.x >> 5;
  const int wm = (w>>2)*32, wn = (w&3)*16;
  float acc[2][2][4];
  #pragma unroll
  for (int a=0;a<2;a++)
    #pragma unroll
    for (int b=0;b<2;b++)
      #pragma unroll
      for (int c=0;c<4;c++) acc[a][b][c]=0.f;

  constexpr int KT = 16;
  stageApk<64>(aHi, aLo, 128, m0, 0, sAhi[0], sAlo[0]);
  stageBpk<64,64>(pkW, 128, 256*128, n0, 0, sBhi[0], sBlo[0]);
  cp_commit();
  for (int kt=0; kt<KT; ++kt){
    if (kt+1 < KT){
      stageApk<64>(aHi, aLo, 128, m0, (kt+1)*16, sAhi[(kt+1)&1], sAlo[(kt+1)&1]);
      stageBpk<64,64>(pkW, 128, 256*128, n0, (kt+1)*16, sBhi[(kt+1)&1], sBlo[(kt+1)&1]);
      cp_commit();
      cp_wait<1>();
    } else {
      cp_wait<0>();
    }
    __syncthreads();
    const int b = kt & 1;
    const int kb = lane & 3;
    unsigned ah[2][4], al[2][4];
    #pragma unroll
    for (int mf=0; mf<2; mf++){
      int ar = (wm + mf*16 + (lane>>2))*12;
      ah[mf][0]=sAhi[b][ar+kb]; ah[mf][1]=sAhi[b][ar+96+kb]; ah[mf][2]=sAhi[b][ar+kb+4]; ah[mf][3]=sAhi[b][ar+96+kb+4];
      al[mf][0]=sAlo[b][ar+kb]; al[mf][1]=sAlo[b][ar+96+kb]; al[mf][2]=sAlo[b][ar+kb+4]; al[mf][3]=sAlo[b][ar+96+kb+4];
    }
    #pragma unroll
    for (int nf=0; nf<2; nf++){
      int br = (wn + nf*8 + (lane>>2))*12;
      unsigned bh0=sBhi[b][br+kb], bh1=sBhi[b][br+kb+4];
      unsigned bl0=sBlo[b][br+kb], bl1=sBlo[b][br+kb+4];
      #pragma unroll
      for (int mf=0; mf<2; mf++){
        mma_bf16(acc[mf][nf], ah[mf][0],ah[mf][1],ah[mf][2],ah[mf][3], bh0,bh1);
        mma_bf16(acc[mf][nf], ah[mf][0],ah[mf][1],ah[mf][2],ah[mf][3], bl0,bl1);
        mma_bf16(acc[mf][nf], al[mf][0],al[mf][1],al[mf][2],al[mf][3], bh0,bh1);
      }
    }
    __syncthreads();
  }
  int mb = m0 + wm + (lane>>2);
  int nb0 = n0 + wn + 2*(lane&3);
  #pragma unroll
  for (int mf=0; mf<2; mf++)
    #pragma unroll
    for (int mr=0; mr<2; mr++){
      int m = mb + mf*16 + mr*8;
      #pragma unroll
      for (int nf=0; nf<2; nf++){
        float o[2];
        #pragma unroll
        for (int c=0; c<2; c++){
          int nn = nb0 + nf*8 + c;
          o[c] = eluf(acc[mf][nf][mr*2+c] + bias[nn]);
        }
        int nn0 = nb0 + nf*8;
        if (MODE == 0){
          *(float2*)(Y + (size_t)m*256 + nn0) = make_float2(o[0], o[1]);
        } else {
          unsigned hi, lo;
          split2(o[0], o[1], hi, lo);
          yHi[(size_t)m*128 + (nn0>>1)] = hi;
          yLo[(size_t)m*128 + (nn0>>1)] = lo;
        }
      }
    }
}

// Action GRU: BM=128, 16 h-cols/block, 4 strips (r,z,in,hn). K=544.
__global__ void __launch_bounds__(256) k_step_act(
    const float* __restrict__ ma, float* __restrict__ haout,
    const unsigned* __restrict__ maHi, const unsigned* __restrict__ maLo,
    const unsigned* __restrict__ fgHi, const unsigned* __restrict__ fgLo,
    unsigned* __restrict__ oHi, unsigned* __restrict__ oLo,
    const float* __restrict__ bih, const float* __restrict__ bhh)
{
  __shared__ __align__(16) unsigned sAhi[2][128*12], sAlo[2][128*12];
  __shared__ __align__(16) unsigned sBhi[2][64*12],  sBlo[2][64*12];
  const int m0 = blockIdx.x*128, n0 = blockIdx.y*16;
  const int lane = threadIdx.x & 31, w = threadIdx.x >> 5;
  float acc[4][2][4];
  #pragma unroll
  for (int s=0;s<4;s++)
    #pragma unroll
    for (int f=0;f<2;f++)
      #pragma unroll
      for (int c=0;c<4;c++) acc[s][f][c]=0.f;

  constexpr int KT = KA/16;   // 34
  stageA_act(maHi, maLo, fgHi, fgLo, m0, 0, sAhi[0], sAlo[0]);
  stageBpk<64,16>(g_pkWcat, 272, 1024*272, n0, 0, sBhi[0], sBlo[0]);
  cp_commit();
  for (int kt=0; kt<KT; ++kt){
    if (kt+1 < KT){
      stageA_act(maHi, maLo, fgHi, fgLo, m0, (kt+1)*16, sAhi[(kt+1)&1], sAlo[(kt+1)&1]);
      stageBpk<64,16>(g_pkWcat, 272, 1024*272, n0, (kt+1)*16, sBhi[(kt+1)&1], sBlo[(kt+1)&1]);
      cp_commit();
      cp_wait<1>();
    } else {
      cp_wait<0>();
    }
    __syncthreads();
    const int b = kt & 1;
    const int arow = (w*16 + (lane>>2))*12;
    const int kb = lane & 3;
    unsigned ah0=sAhi[b][arow+kb], ah1=sAhi[b][arow+96+kb], ah2=sAhi[b][arow+kb+4], ah3=sAhi[b][arow+96+kb+4];
    unsigned al0=sAlo[b][arow+kb], al1=sAlo[b][arow+96+kb], al2=sAlo[b][arow+kb+4], al3=sAlo[b][arow+96+kb+4];
    #pragma unroll
    for (int s=0;s<4;s++){
      #pragma unroll
      for (int f=0;f<2;f++){
        int brow = (s*16 + f*8 + (lane>>2))*12;
        unsigned bh0=sBhi[b][brow+kb], bh1=sBhi[b][brow+kb+4];
        unsigned bl0=sBlo[b][brow+kb], bl1=sBlo[b][brow+kb+4];
        mma_bf16(acc[s][f], ah0,ah1,ah2,ah3, bh0,bh1);
        mma_bf16(acc[s][f], ah0,ah1,ah2,ah3, bl0,bl1);
        mma_bf16(acc[s][f], al0,al1,al2,al3, bh0,bh1);
      }
    }
    __syncthreads();
  }
  int mb = m0 + w*16 + (lane>>2);
  int jb0 = 2*(lane&3);
  #pragma unroll
  for (int mr=0; mr<2; mr++){
    int m = mb + mr*8;
    #pragma unroll
    for (int f=0; f<2; f++){
      float o[2];
      #pragma unroll
      for (int c=0; c<2; c++){
        int j = n0 + jb0 + f*8 + c;
        int ci = mr*2 + c;
        float r = sigf(acc[0][f][ci] + bih[j]     + bhh[j]);
        float z = sigf(acc[1][f][ci] + bih[256+j] + bhh[256+j]);
        float n = tanhf(acc[2][f][ci] + bih[512+j] + r*(acc[3][f][ci] + bhh[512+j]));
        o[c] = (1.f - z)*n + z*ma[(size_t)m*256 + j];
      }
      int j0 = n0 + jb0 + f*8;
      *(float2*)(haout + (size_t)m*256 + j0) = make_float2(o[0], o[1]);
      unsigned hi, lo;
      split2(o[0], o[1], hi, lo);
      oHi[(size_t)m*128 + (j0>>1)] = hi;
      oLo[(size_t)m*128 + (j0>>1)] = lo;
    }
  }
}

// ---------------- small kernels ----------------
// max over E entities + pack feat directly into catFG (cols 0..127 of the FG region)
__global__ void k_maxpoolpack(const float* __restrict__ proc){
  int g = blockIdx.x;       // 0..2047
  int c = threadIdx.x;      // 0..127 (col pair)
  const float* p = proc + (size_t)g*NE*256;
  float v0 = p[2*c], v1 = p[2*c+1];
  #pragma unroll
  for (int e=1;e<NE;e++){
    v0 = fmaxf(v0, p[e*256 + 2*c]);
    v1 = fmaxf(v1, p[e*256 + 2*c + 1]);
  }
  unsigned hi, lo;
  split2(v0, v1, hi, lo);
  g_catFG[(size_t)g*K2FG + c] = hi;
  g_catFG[(size_t)MA_*K2FG + (size_t)g*K2FG + c] = lo;
}

// movement head: out = tanh(m1 @ W2^T + b2) * 0.05 ; one warp per row
__global__ void k_move(const float* __restrict__ m1, const float* __restrict__ W2,
                       const float* __restrict__ b2, float* __restrict__ out){
  int warp = (blockIdx.x*blockDim.x + threadIdx.x) >> 5;
  int lane = threadIdx.x & 31;
  if (warp >= MA_) return;
  const float* x = m1 + (size_t)warp*256;
  float s0 = 0.f, s1 = 0.f;
  #pragma unroll
  for (int k=lane; k<256; k+=32){
    float xv = x[k];
    s0 = fmaf(xv, W2[k],       s0);
    s1 = fmaf(xv, W2[256 + k], s1);
  }
  #pragma unroll
  for (int o=16;o>0;o>>=1){
    s0 += __shfl_down_sync(0xffffffffu, s0, o);
    s1 += __shfl_down_sync(0xffffffffu, s1, o);
  }
  if (lane == 0){
    out[warp*2 + 0] = tanhf(s0 + b2[0]) * 0.05f;
    out[warp*2 + 1] = tanhf(s1 + b2[1]) * 0.05f;
  }
}

// ---------------- launch ----------------
extern "C" void kernel_launch(void* const* d_in, const int* in_sizes, int n_in,
                              void* d_out, int out_size){
  (void)in_sizes; (void)n_in; (void)out_size;
  const float* obs  = (const float*)d_in[0];
  const float* phys = (const float*)d_in[1];
  const float* goals= (const float*)d_in[2];
  const float* memp = (const float*)d_in[3];
  const float* mema = (const float*)d_in[4];
  const float* Wihp = (const float*)d_in[5];
  const float* Whhp = (const float*)d_in[6];
  const float* bihp = (const float*)d_in[7];
  const float* bhhp = (const float*)d_in[8];
  const float* Wfcp = (const float*)d_in[9];
  const float* bfcp = (const float*)d_in[10];
  const float* Wiha = (const float*)d_in[11];
  const float* Whha = (const float*)d_in[12];
  const float* biha = (const float*)d_in[13];
  const float* bhha = (const float*)d_in[14];
  const float* Wfca = (const float*)d_in[15];
  const float* bfca = (const float*)d_in[16];
  const float* Wm1  = (const float*)d_in[17];
  const float* bm1  = (const float*)d_in[18];
  const float* Wm2  = (const float*)d_in[19];
  const float* bm2  = (const float*)d_in[20];
  float* out = (float*)d_out;

  float *Pmp, *Pma, *Pproc, *Pm1;
  unsigned *PpkMp, *PpkMan, *PpkProca, *PcatFG;
  unsigned *PpkWhh, *PpkWfcP, *PpkWfcA, *PpkWm1, *PpkWcat;
  cudaGetSymbolAddress((void**)&Pmp,     g_mp);
  cudaGetSymbolAddress((void**)&Pma,     g_ma);
  cudaGetSymbolAddress((void**)&Pproc,   g_proc);
  cudaGetSymbolAddress((void**)&Pm1,     g_m1);
  cudaGetSymbolAddress((void**)&PpkMp,   g_pkMp);
  cudaGetSymbolAddress((void**)&PpkMan,  g_pkMan);
  cudaGetSymbolAddress((void**)&PpkProca,g_pkProca);
  cudaGetSymbolAddress((void**)&PcatFG,  g_catFG);
  cudaGetSymbolAddress((void**)&PpkWhh,  g_pkWhh);
  cudaGetSymbolAddress((void**)&PpkWfcP, g_pkWfcP);
  cudaGetSymbolAddress((void**)&PpkWfcA, g_pkWfcA);
  cudaGetSymbolAddress((void**)&PpkWm1,  g_pkWm1);
  cudaGetSymbolAddress((void**)&PpkWcat, g_pkWcat);

  const size_t SMP = (size_t)MP*128;    // plane size (uint32) for phys activations
  const size_t SMA = (size_t)MA_*128;

  // init fp32 recurrent state (buffer 0)
  cudaMemcpyAsync(Pmp, memp, (size_t)MP *NH*sizeof(float), cudaMemcpyDeviceToDevice);
  cudaMemcpyAsync(Pma, mema, (size_t)MA_*NH*sizeof(float), cudaMemcpyDeviceToDevice);

  // precompute packed weights, packed initial states, goals, time-invariant gi
  k_packW   <<<(768*128+255)/256, 256>>>(Whhp, PpkWhh, 768, 256);
  k_packW   <<<(256*128+255)/256, 256>>>(Wfcp, PpkWfcP, 256, 256);
  k_packW   <<<(256*128+255)/256, 256>>>(Wfca, PpkWfcA, 256, 256);
  k_packW   <<<(256*128+255)/256, 256>>>(Wm1,  PpkWm1,  256, 256);
  k_packWcat<<<(1024*272+255)/256,256>>>(Wiha, Whha, PpkWcat);
  k_packAct <<<(MP*128+255)/256,  256>>>(memp, PpkMp,  PpkMp  + SMP, MP*128);
  k_packAct <<<(MA_*128+255)/256, 256>>>(mema, PpkMan, PpkMan + SMA, MA_*128);
  k_packGoals<<<(MA_*16+255)/256, 256>>>(goals);
  k_giP<<<MP,256>>>(obs, phys, Wihp, bihp, bhhp);

  for (int t=0;t<NT;t++){
    int cur = t & 1, nxt = cur ^ 1;
    float* mpc = Pmp + (size_t)cur*MP *NH;
    float* mpn = Pmp + (size_t)nxt*MP *NH;
    float* mac = Pma + (size_t)cur*MA_*NH;
    float* man = Pma + (size_t)nxt*MA_*NH;
    unsigned* mpPkC = PpkMp  + (size_t)cur*2*SMP;
    unsigned* mpPkN = PpkMp  + (size_t)nxt*2*SMP;
    unsigned* maPkC = PpkMan + (size_t)cur*2*SMA;
    unsigned* maPkN = PpkMan + (size_t)nxt*2*SMA;

    k_step_phys<<<dim3(MP/128, 8), 256>>>(mpc, mpn, mpPkC, mpPkC + SMP,
                                          mpPkN, mpPkN + SMP, bhhp);
    k_fc_elu<0><<<dim3(MP/64, 4), 256>>>(mpPkN, mpPkN + SMP, PpkWfcP, bfcp,
                                         Pproc, nullptr, nullptr);
    k_maxpoolpack<<<MA_, 128>>>(Pproc);
    k_step_act<<<dim3(MA_/128, 16), 256>>>(mac, man, maPkC, maPkC + SMA,
                                           PcatFG, PcatFG + (size_t)MA_*K2FG,
                                           maPkN, maPkN + SMA, biha, bhha);
    k_fc_elu<1><<<dim3(MA_/64, 4), 256>>>(maPkN, maPkN + SMA, PpkWfcA, bfca,
                                          nullptr, PpkProca, PpkProca + SMA);
    k_fc_elu<0><<<dim3(MA_/64, 4), 256>>>(PpkProca, PpkProca + SMA, PpkWm1, bm1,
                                          Pm1, nullptr, nullptr);
    k_move<<<MA_/8, 256>>>(Pm1, Wm2, bm2, out + (size_t)t*MA_*NMV);
  }
}